// round 13
// baseline (speedup 1.0000x reference)
#include <cuda_runtime.h>
#include <cuda_fp16.h>
#include <math.h>
#include <stdint.h>

#define T_TOK 4096
#define DIM   2048
#define FFN   5632
#define NE    8
#define NSLOT (T_TOK*2)

// ---------------- device scratch --------------------------------------------
__device__ int    g_counts[NE];
__device__ int    g_offsets[NE];
__device__ int    g_fill[NE];
__device__ int    g_route_idx[NSLOT];
__device__ float  g_route_w[NSLOT];
__device__ int    g_sorted_tok[NSLOT];
__device__ float  g_sorted_w[NSLOT];
__device__ __half g_xh[(size_t)T_TOK * DIM];   // 16.8 MB (x in fp16)
__device__ __half g_hh[(size_t)NSLOT * FFN];   // 92 MB   (h in fp16)

// ---------------- helpers ----------------------------------------------------
__device__ __forceinline__ uint32_t smem_u32(const void* p) {
    uint32_t a;
    asm("{ .reg .u64 t; cvta.to.shared.u64 t, %1; cvt.u32.u64 %0, t; }"
        : "=r"(a) : "l"(p));
    return a;
}
__device__ __forceinline__ void cp16g(uint32_t saddr, const void* g) {
    asm volatile("cp.async.cg.shared.global [%0], [%1], 16;"
                 :: "r"(saddr), "l"(g) : "memory");
}
__device__ __forceinline__ void cp_commit() {
    asm volatile("cp.async.commit_group;" ::: "memory");
}
__device__ __forceinline__ void cp_wait1() {
    asm volatile("cp.async.wait_group 1;" ::: "memory");
}
__device__ __forceinline__ void mma_f16(float c[4], uint32_t a0, uint32_t a1,
                                        uint32_t a2, uint32_t a3,
                                        uint32_t b0, uint32_t b1) {
    asm volatile(
        "mma.sync.aligned.m16n8k16.row.col.f32.f16.f16.f32 "
        "{%0,%1,%2,%3},{%4,%5,%6,%7},{%8,%9},{%0,%1,%2,%3};\n"
        : "+f"(c[0]), "+f"(c[1]), "+f"(c[2]), "+f"(c[3])
        : "r"(a0), "r"(a1), "r"(a2), "r"(a3), "r"(b0), "r"(b1));
}
__device__ __forceinline__ uint32_t packh2(float lo, float hi) {
    __half2 h = __floats2half2_rn(lo, hi);
    return *(uint32_t*)&h;
}

// ---------------- conversion: fp32 -> fp16 (x only) ---------------------------
__global__ void cvt_kernel(const float* __restrict__ src,
                           __half* __restrict__ dst, int n4) {
    int i = blockIdx.x * blockDim.x + threadIdx.x;
    if (i < n4) {
        float4 v = ((const float4*)src)[i];
        __half2 h0 = __floats2half2_rn(v.x, v.y);
        __half2 h1 = __floats2half2_rn(v.z, v.w);
        uint2 o;
        o.x = *(uint32_t*)&h0;
        o.y = *(uint32_t*)&h1;
        ((uint2*)dst)[i] = o;
    }
}

// ---------------- small kernels (routing) ------------------------------------
__global__ void zero_kernel() {
    if (threadIdx.x < NE) g_counts[threadIdx.x] = 0;
}

__global__ void router_kernel(const float* __restrict__ x,
                              const float* __restrict__ gw) {
    int t = blockIdx.x;
    const float* xr = x + (size_t)t * DIM;
    float p[NE];
#pragma unroll
    for (int e = 0; e < NE; e++) p[e] = 0.f;
    for (int d = threadIdx.x; d < DIM; d += 256) {
        float xv = xr[d];
#pragma unroll
        for (int e = 0; e < NE; e++) p[e] += xv * gw[e * DIM + d];
    }
    __shared__ float red[8][NE];
    int warp = threadIdx.x >> 5, lane = threadIdx.x & 31;
#pragma unroll
    for (int e = 0; e < NE; e++) {
        float v = p[e];
#pragma unroll
        for (int o = 16; o > 0; o >>= 1) v += __shfl_xor_sync(0xffffffffu, v, o);
        if (lane == 0) red[warp][e] = v;
    }
    __syncthreads();
    if (threadIdx.x == 0) {
        float logit[NE];
#pragma unroll
        for (int e = 0; e < NE; e++) {
            float s = 0.f;
#pragma unroll
            for (int w = 0; w < 8; w++) s += red[w][e];
            logit[e] = s;
        }
        int i0 = 0; float v0 = logit[0];
        int i1 = -1; float v1 = -INFINITY;
#pragma unroll
        for (int e = 1; e < NE; e++) {
            float v = logit[e];
            if (v > v0)      { v1 = v0; i1 = i0; v0 = v; i0 = e; }
            else if (v > v1) { v1 = v;  i1 = e; }
        }
        float e1 = expf(v1 - v0);
        float s  = 1.f + e1;
        g_route_idx[t * 2 + 0] = i0;  g_route_w[t * 2 + 0] = 1.f / s;
        g_route_idx[t * 2 + 1] = i1;  g_route_w[t * 2 + 1] = e1 / s;
        atomicAdd(&g_counts[i0], 1);
        atomicAdd(&g_counts[i1], 1);
    }
}

__global__ void scan_kernel() {
    if (threadIdx.x == 0) {
        int off = 0;
        for (int e = 0; e < NE; e++) {
            g_offsets[e] = off;
            g_fill[e]    = off;
            off += g_counts[e];
        }
    }
}

__global__ void scatter_kernel() {
    int t = blockIdx.x * blockDim.x + threadIdx.x;
    if (t >= T_TOK) return;
#pragma unroll
    for (int k = 0; k < 2; k++) {
        int e = g_route_idx[t * 2 + k];
        int p = atomicAdd(&g_fill[e], 1);
        g_sorted_tok[p] = t;
        g_sorted_w[p]   = g_route_w[t * 2 + k];
    }
}

__global__ void init_out_kernel(float* __restrict__ out,
                                const float* __restrict__ bias) {
    int i = blockIdx.x * blockDim.x + threadIdx.x;
    if (i < T_TOK * DIM) out[i] = bias[i & (DIM - 1)];
}

// ---------------- GEMM config ------------------------------------------------
// CTA 128(M) x 128(N), KC=32, 256 thr, 8 warps (2M x 4N), warp 64x32.
// fp16 A tiles: pitch 40 halfs (80 B). fp32 B tiles: pitch 36 floats (144 B).
#define KC      32
#define HPITCH  40
#define HROWB   (HPITCH*2)       // 80 B
#define FPITCH  36
#define FROWB   (FPITCH*4)       // 144 B
#define ATILEB  (128*HROWB)      // 10240 B (fp16 tile)
#define BTILEB  (128*FROWB)      // 18432 B (fp32 tile)
#define ST1B    (ATILEB + 2*BTILEB)   // gemm1 stage = 47104
#define ST2B    (ATILEB + BTILEB)     // gemm2 stage = 28672
#define SMEM1   (2*ST1B + 512)        // 94720 (2-stage)
#define SMEM2   (3*ST2B + 1024)       // 87040 (3-stage)

// ---------------- gemm1: h = silu(X Wg^T) * (X Wu^T) -------------------------
// A = x (fp16, gathered), Bg/Bu = weights loaded DIRECTLY as fp32.
__global__ __launch_bounds__(256, 1) void gemm1_kernel(
    const float* __restrict__ wgate,
    const float* __restrict__ wup) {
    int e = blockIdx.z;
    int cnt = g_counts[e];
    int mbase = blockIdx.y * 128;
    if (mbase >= cnt) return;
    int off = g_offsets[e];
    int nbase = blockIdx.x * 128;

    extern __shared__ char sm[];
    uint32_t sb = smem_u32(sm);
    int* stok = (int*)(sm + 2 * ST1B);
    int tid = threadIdx.x;

    if (tid < 128) {
        int m = mbase + tid;
        stok[tid] = g_sorted_tok[off + (m < cnt ? m : cnt - 1)];
    }
    __syncthreads();

    const float* wgE = wgate + (size_t)e * FFN * DIM + (size_t)nbase * DIM;
    const float* wuE = wup   + (size_t)e * FFN * DIM + (size_t)nbase * DIM;

    // A fp16: 512 segs of 16B (4/row); B fp32: 1024 segs of 16B (8/row)
    const __half* paA[2];
    uint32_t soA[2];
#pragma unroll
    for (int j = 0; j < 2; j++) {
        int s = tid + j * 256;
        int r = s >> 2, sg = s & 3;
        paA[j] = g_xh + (size_t)stok[r] * DIM + sg * 8;
        soA[j] = (uint32_t)(r * HROWB + sg * 16);
    }
    const float *pg[4], *pu[4];
    uint32_t soB[4];
#pragma unroll
    for (int j = 0; j < 4; j++) {
        int s = tid + j * 256;
        int r = s >> 3, sg = s & 7;
        pg[j] = wgE + (size_t)r * DIM + sg * 4;
        pu[j] = wuE + (size_t)r * DIM + sg * 4;
        soB[j] = (uint32_t)(r * FROWB + sg * 16);
    }

#define ISSUE1(k0, s)                                                       \
    do {                                                                    \
        uint32_t base = sb + (s) * ST1B;                                    \
        _Pragma("unroll")                                                   \
        for (int j = 0; j < 2; j++)                                         \
            cp16g(base + soA[j], paA[j] + (k0));                            \
        _Pragma("unroll")                                                   \
        for (int j = 0; j < 4; j++) {                                       \
            cp16g(base + ATILEB + soB[j],          pg[j] + (k0));           \
            cp16g(base + ATILEB + BTILEB + soB[j], pu[j] + (k0));           \
        }                                                                   \
        cp_commit();                                                        \
    } while (0)

    int warp = tid >> 5, lane = tid & 31;
    int wm = warp >> 2, wn = warp & 3;        // 2 x 4
    int lr = lane >> 2, lc = lane & 3;

    float cg[4][4][4], cu[4][4][4];
#pragma unroll
    for (int a = 0; a < 4; a++)
#pragma unroll
        for (int b = 0; b < 4; b++)
#pragma unroll
            for (int r = 0; r < 4; r++) { cg[a][b][r] = 0.f; cu[a][b][r] = 0.f; }

    ISSUE1(0, 0);

    const int NK = DIM / KC;   // 64
#pragma unroll 1
    for (int kt = 0; kt < NK; kt++) {
        if (kt + 1 < NK) {
            ISSUE1((kt + 1) * KC, (kt + 1) & 1);
        } else {
            cp_commit();
        }
        cp_wait1();
        __syncthreads();
        int s = kt & 1;
        const __half (*As)[HPITCH] = (const __half (*)[HPITCH])(sm + s * ST1B);
        const float (*Bg)[FPITCH] = (const float (*)[FPITCH])(sm + s * ST1B + ATILEB);
        const float (*Bu)[FPITCH] = (const float (*)[FPITCH])(sm + s * ST1B + ATILEB + BTILEB);
#pragma unroll
        for (int kk = 0; kk < 2; kk++) {
            int kb = kk * 16;
            int ch = kb + 2 * lc;      // half index for A
            uint32_t a[4][4];
#pragma unroll
            for (int mf = 0; mf < 4; mf++) {
                int r = wm * 64 + mf * 16 + lr;
                a[mf][0] = *(const uint32_t*)&As[r][ch];
                a[mf][1] = *(const uint32_t*)&As[r + 8][ch];
                a[mf][2] = *(const uint32_t*)&As[r][ch + 8];
                a[mf][3] = *(const uint32_t*)&As[r + 8][ch + 8];
            }
#pragma unroll
            for (int nf = 0; nf < 4; nf++) {
                int col = wn * 32 + nf * 8 + lr;
                float2 g0 = *(const float2*)&Bg[col][ch];
                float2 g1 = *(const float2*)&Bg[col][ch + 8];
                float2 u0 = *(const float2*)&Bu[col][ch];
                float2 u1 = *(const float2*)&Bu[col][ch + 8];
                uint32_t bg0 = packh2(g0.x, g0.y), bg1 = packh2(g1.x, g1.y);
                uint32_t bu0 = packh2(u0.x, u0.y), bu1 = packh2(u1.x, u1.y);
#pragma unroll
                for (int mf = 0; mf < 4; mf++) {
                    mma_f16(cg[mf][nf], a[mf][0], a[mf][1], a[mf][2], a[mf][3], bg0, bg1);
                    mma_f16(cu[mf][nf], a[mf][0], a[mf][1], a[mf][2], a[mf][3], bu0, bu1);
                }
            }
        }
        __syncthreads();
    }

    // epilogue: h = silu(g) * u -> fp16
#pragma unroll
    for (int mf = 0; mf < 4; mf++) {
#pragma unroll
        for (int half = 0; half < 2; half++) {
            int mrow = wm * 64 + mf * 16 + lr + half * 8;
            int m = mbase + mrow;
            if (m < cnt) {
                __half* hp = g_hh + (size_t)(off + m) * FFN + nbase + wn * 32;
#pragma unroll
                for (int nf = 0; nf < 4; nf++) {
                    float g0 = cg[mf][nf][half * 2 + 0];
                    float g1 = cg[mf][nf][half * 2 + 1];
                    float u0 = cu[mf][nf][half * 2 + 0];
                    float u1 = cu[mf][nf][half * 2 + 1];
                    float h0 = u0 * g0 / (1.f + __expf(-g0));
                    float h1 = u1 * g1 / (1.f + __expf(-g1));
                    *(__half2*)(hp + nf * 8 + lc * 2) = __floats2half2_rn(h0, h1);
                }
            }
        }
    }
#undef ISSUE1
}

// ---------------- gemm2: out += w * (h Wo^T) ---------------------------------
// A = h (fp16), B = Wo loaded DIRECTLY as fp32. 3-stage pipeline.
__global__ __launch_bounds__(256, 1) void gemm2_kernel(
    const float* __restrict__ wout,
    float* __restrict__ out) {
    int e = blockIdx.z;
    int cnt = g_counts[e];
    int mbase = blockIdx.y * 128;
    if (mbase >= cnt) return;
    int off = g_offsets[e];
    int nbase = blockIdx.x * 128;

    extern __shared__ char sm[];
    uint32_t sb = smem_u32(sm);
    int*   stok = (int*)(sm + 3 * ST2B);
    float* swt  = (float*)(sm + 3 * ST2B + 512);
    int tid = threadIdx.x;

    if (tid < 128) {
        int m = mbase + tid;
        int mc = m < cnt ? m : cnt - 1;
        stok[tid] = g_sorted_tok[off + mc];
        swt[tid]  = (m < cnt) ? g_sorted_w[off + m] : 0.f;
    }
    __syncthreads();

    const float* woE = wout + (size_t)e * DIM * FFN + (size_t)nbase * FFN;

    const __half* paA[2];
    uint32_t soA[2];
#pragma unroll
    for (int j = 0; j < 2; j++) {
        int s = tid + j * 256;
        int r = s >> 2, sg = s & 3;
        int mc = mbase + r; if (mc > cnt - 1) mc = cnt - 1;
        paA[j] = g_hh + (size_t)(off + mc) * FFN + sg * 8;
        soA[j] = (uint32_t)(r * HROWB + sg * 16);
    }
    const float* pb[4];
    uint32_t soB[4];
#pragma unroll
    for (int j = 0; j < 4; j++) {
        int s = tid + j * 256;
        int r = s >> 3, sg = s & 7;
        pb[j] = woE + (size_t)r * FFN + sg * 4;
        soB[j] = (uint32_t)(r * FROWB + sg * 16);
    }

#define ISSUE2(k0, s)                                                       \
    do {                                                                    \
        uint32_t base = sb + (s) * ST2B;                                    \
        _Pragma("unroll")                                                   \
        for (int j = 0; j < 2; j++)                                         \
            cp16g(base + soA[j], paA[j] + (k0));                            \
        _Pragma("unroll")                                                   \
        for (int j = 0; j < 4; j++)                                         \
            cp16g(base + ATILEB + soB[j], pb[j] + (k0));                    \
        cp_commit();                                                        \
    } while (0)

    int warp = tid >> 5, lane = tid & 31;
    int wm = warp >> 2, wn = warp & 3;
    int lr = lane >> 2, lc = lane & 3;

    float cc[4][4][4];
#pragma unroll
    for (int a = 0; a < 4; a++)
#pragma unroll
        for (int b = 0; b < 4; b++)
#pragma unroll
            for (int r = 0; r < 4; r++) cc[a][b][r] = 0.f;

    ISSUE2(0, 0);
    ISSUE2(KC, 1);

    const int NK = FFN / KC;   // 176
#pragma unroll 1
    for (int kt = 0; kt < NK; kt++) {
        cp_wait1();
        __syncthreads();
        if (kt + 2 < NK) {
            ISSUE2((kt + 2) * KC, (kt + 2) % 3);
        } else {
            cp_commit();
        }
        int s = kt % 3;
        const __half (*As)[HPITCH] = (const __half (*)[HPITCH])(sm + s * ST2B);
        const float (*Bs)[FPITCH] = (const float (*)[FPITCH])(sm + s * ST2B + ATILEB);
#pragma unroll
        for (int kk = 0; kk < 2; kk++) {
            int kb = kk * 16;
            int ch = kb + 2 * lc;
            uint32_t a[4][4];
#pragma unroll
            for (int mf = 0; mf < 4; mf++) {
                int r = wm * 64 + mf * 16 + lr;
                a[mf][0] = *(const uint32_t*)&As[r][ch];
                a[mf][1] = *(const uint32_t*)&As[r + 8][ch];
                a[mf][2] = *(const uint32_t*)&As[r][ch + 8];
                a[mf][3] = *(const uint32_t*)&As[r + 8][ch + 8];
            }
#pragma unroll
            for (int nf = 0; nf < 4; nf++) {
                int col = wn * 32 + nf * 8 + lr;
                float2 w0 = *(const float2*)&Bs[col][ch];
                float2 w1 = *(const float2*)&Bs[col][ch + 8];
                uint32_t b0 = packh2(w0.x, w0.y), b1 = packh2(w1.x, w1.y);
#pragma unroll
                for (int mf = 0; mf < 4; mf++)
                    mma_f16(cc[mf][nf], a[mf][0], a[mf][1], a[mf][2], a[mf][3], b0, b1);
            }
        }
    }

    // epilogue: out += w * y
#pragma unroll
    for (int mf = 0; mf < 4; mf++) {
#pragma unroll
        for (int half = 0; half < 2; half++) {
            int mrow = wm * 64 + mf * 16 + lr + half * 8;
            int m = mbase + mrow;
            if (m < cnt) {
                float wgt = swt[mrow];
                float* op = out + (size_t)stok[mrow] * DIM + nbase + wn * 32;
#pragma unroll
                for (int nf = 0; nf < 4; nf++) {
                    atomicAdd(op + nf * 8 + lc * 2,     cc[mf][nf][half * 2 + 0] * wgt);
                    atomicAdd(op + nf * 8 + lc * 2 + 1, cc[mf][nf][half * 2 + 1] * wgt);
                }
            }
        }
    }
#undef ISSUE2
}

// ---------------- launch -----------------------------------------------------
extern "C" void kernel_launch(void* const* d_in, const int* in_sizes, int n_in,
                              void* d_out, int out_size) {
    const float* x    = (const float*)d_in[0];
    const float* gw   = (const float*)d_in[1];
    const float* wg   = (const float*)d_in[2];
    const float* wu   = (const float*)d_in[3];
    const float* wo   = (const float*)d_in[4];
    const float* bias = (const float*)d_in[5];
    float* out = (float*)d_out;

    cudaFuncSetAttribute(gemm1_kernel, cudaFuncAttributeMaxDynamicSharedMemorySize, SMEM1);
    cudaFuncSetAttribute(gemm2_kernel, cudaFuncAttributeMaxDynamicSharedMemorySize, SMEM2);

    __half* xh;
    cudaGetSymbolAddress((void**)&xh, g_xh);
    const int nX4 = T_TOK * DIM / 4;

    zero_kernel<<<1, 32>>>();
    router_kernel<<<T_TOK, 256>>>(x, gw);
    scan_kernel<<<1, 32>>>();
    scatter_kernel<<<(T_TOK + 255) / 256, 256>>>();
    init_out_kernel<<<(T_TOK * DIM) / 256, 256>>>(out, bias);
    cvt_kernel<<<nX4 / 256, 256>>>(x, xh, nX4);
    gemm1_kernel<<<dim3(FFN / 128, T_TOK / 128, NE), 256, SMEM1>>>(wg, wu);
    gemm2_kernel<<<dim3(DIM / 128, T_TOK / 128, NE), 256, SMEM2>>>(wo, out);
}

// round 16
// speedup vs baseline: 1.0761x; 1.0761x over previous
#include <cuda_runtime.h>
#include <cuda_fp16.h>
#include <math.h>
#include <stdint.h>

#define T_TOK 4096
#define DIM   2048
#define FFN   5632
#define NE    8
#define NSLOT (T_TOK*2)

// ---------------- device scratch --------------------------------------------
__device__ int    g_counts[NE];
__device__ int    g_offsets[NE];
__device__ int    g_fill[NE];
__device__ int    g_route_idx[NSLOT];
__device__ float  g_route_w[NSLOT];
__device__ int    g_sorted_tok[NSLOT];
__device__ float  g_sorted_w[NSLOT];
__device__ __half g_xh[(size_t)T_TOK * DIM];     // 16.8 MB
__device__ __half g_wgh[(size_t)NE * FFN * DIM]; // 184 MB
__device__ __half g_wuh[(size_t)NE * FFN * DIM]; // 184 MB
__device__ __half g_hh[(size_t)NSLOT * FFN];     // 92 MB

// ---------------- helpers ----------------------------------------------------
__device__ __forceinline__ uint32_t smem_u32(const void* p) {
    uint32_t a;
    asm("{ .reg .u64 t; cvta.to.shared.u64 t, %1; cvt.u32.u64 %0, t; }"
        : "=r"(a) : "l"(p));
    return a;
}
__device__ __forceinline__ void cp8(uint32_t saddr, const void* g) {
    asm volatile("cp.async.ca.shared.global [%0], [%1], 8;"
                 :: "r"(saddr), "l"(g) : "memory");
}
__device__ __forceinline__ void cp16g(uint32_t saddr, const void* g) {
    asm volatile("cp.async.cg.shared.global [%0], [%1], 16;"
                 :: "r"(saddr), "l"(g) : "memory");
}
__device__ __forceinline__ void cp_commit() {
    asm volatile("cp.async.commit_group;" ::: "memory");
}
__device__ __forceinline__ void cp_wait1() {
    asm volatile("cp.async.wait_group 1;" ::: "memory");
}
__device__ __forceinline__ void mma_f16(float c[4], uint32_t a0, uint32_t a1,
                                        uint32_t a2, uint32_t a3,
                                        uint32_t b0, uint32_t b1) {
    asm volatile(
        "mma.sync.aligned.m16n8k16.row.col.f32.f16.f16.f32 "
        "{%0,%1,%2,%3},{%4,%5,%6,%7},{%8,%9},{%0,%1,%2,%3};\n"
        : "+f"(c[0]), "+f"(c[1]), "+f"(c[2]), "+f"(c[3])
        : "r"(a0), "r"(a1), "r"(a2), "r"(a3), "r"(b0), "r"(b1));
}
__device__ __forceinline__ uint32_t packh2(float lo, float hi) {
    __half2 h = __floats2half2_rn(lo, hi);
    return *(uint32_t*)&h;
}

// ---------------- conversion kernels -----------------------------------------
__global__ void cvt_kernel(const float* __restrict__ src,
                           __half* __restrict__ dst, int n4) {
    int i = blockIdx.x * blockDim.x + threadIdx.x;
    if (i < n4) {
        float4 v = ((const float4*)src)[i];
        __half2 h0 = __floats2half2_rn(v.x, v.y);
        __half2 h1 = __floats2half2_rn(v.z, v.w);
        uint2 o;
        o.x = *(uint32_t*)&h0;
        o.y = *(uint32_t*)&h1;
        ((uint2*)dst)[i] = o;
    }
}

// converts wg and wu in a single launch (grid = 2*n4/256)
__global__ void cvt2_kernel(const float* __restrict__ s1, __half* __restrict__ d1,
                            const float* __restrict__ s2, __half* __restrict__ d2,
                            int n4) {
    int i = blockIdx.x * blockDim.x + threadIdx.x;
    const float* s = (i < n4) ? s1 : s2;
    __half* d      = (i < n4) ? d1 : d2;
    int k = (i < n4) ? i : i - n4;
    float4 v = ((const float4*)s)[k];
    __half2 h0 = __floats2half2_rn(v.x, v.y);
    __half2 h1 = __floats2half2_rn(v.z, v.w);
    uint2 o;
    o.x = *(uint32_t*)&h0;
    o.y = *(uint32_t*)&h1;
    ((uint2*)d)[k] = o;
}

// ---------------- small kernels (routing) ------------------------------------
__global__ void zero_kernel() {
    if (threadIdx.x < NE) g_counts[threadIdx.x] = 0;
}

__global__ void router_kernel(const float* __restrict__ x,
                              const float* __restrict__ gw) {
    int t = blockIdx.x;
    const float* xr = x + (size_t)t * DIM;
    float p[NE];
#pragma unroll
    for (int e = 0; e < NE; e++) p[e] = 0.f;
    for (int d = threadIdx.x; d < DIM; d += 256) {
        float xv = xr[d];
#pragma unroll
        for (int e = 0; e < NE; e++) p[e] += xv * gw[e * DIM + d];
    }
    __shared__ float red[8][NE];
    int warp = threadIdx.x >> 5, lane = threadIdx.x & 31;
#pragma unroll
    for (int e = 0; e < NE; e++) {
        float v = p[e];
#pragma unroll
        for (int o = 16; o > 0; o >>= 1) v += __shfl_xor_sync(0xffffffffu, v, o);
        if (lane == 0) red[warp][e] = v;
    }
    __syncthreads();
    if (threadIdx.x == 0) {
        float logit[NE];
#pragma unroll
        for (int e = 0; e < NE; e++) {
            float s = 0.f;
#pragma unroll
            for (int w = 0; w < 8; w++) s += red[w][e];
            logit[e] = s;
        }
        int i0 = 0; float v0 = logit[0];
        int i1 = -1; float v1 = -INFINITY;
#pragma unroll
        for (int e = 1; e < NE; e++) {
            float v = logit[e];
            if (v > v0)      { v1 = v0; i1 = i0; v0 = v; i0 = e; }
            else if (v > v1) { v1 = v;  i1 = e; }
        }
        float e1 = expf(v1 - v0);
        float s  = 1.f + e1;
        g_route_idx[t * 2 + 0] = i0;  g_route_w[t * 2 + 0] = 1.f / s;
        g_route_idx[t * 2 + 1] = i1;  g_route_w[t * 2 + 1] = e1 / s;
        atomicAdd(&g_counts[i0], 1);
        atomicAdd(&g_counts[i1], 1);
    }
}

__global__ void scan_kernel() {
    if (threadIdx.x == 0) {
        int off = 0;
        for (int e = 0; e < NE; e++) {
            g_offsets[e] = off;
            g_fill[e]    = off;
            off += g_counts[e];
        }
    }
}

__global__ void scatter_kernel() {
    int t = blockIdx.x * blockDim.x + threadIdx.x;
    if (t >= T_TOK) return;
#pragma unroll
    for (int k = 0; k < 2; k++) {
        int e = g_route_idx[t * 2 + k];
        int p = atomicAdd(&g_fill[e], 1);
        g_sorted_tok[p] = t;
        g_sorted_w[p]   = g_route_w[t * 2 + k];
    }
}

__global__ void init_out_kernel(float* __restrict__ out,
                                const float* __restrict__ bias) {
    int i = blockIdx.x * blockDim.x + threadIdx.x;
    if (i < T_TOK * DIM) out[i] = bias[i & (DIM - 1)];
}

// ---------------- GEMM config ------------------------------------------------
// CTA 128(M) x 128(N), KC=32, 256 thr, 8 warps (2M x 4N), warp 64x32.
// fp16 tiles: pitch 40 halfs (80 B). fp32 tile (gemm2 B): pitch 36 floats.
#define KC      32
#define HPITCH  40
#define HROWB   (HPITCH*2)       // 80 B
#define FPITCH  36
#define FROWB   (FPITCH*4)       // 144 B
#define ATILEB  (128*HROWB)      // 10240 B fp16 tile
#define BTILEB  (128*FROWB)      // 18432 B fp32 tile
#define ST1B    (3*ATILEB)       // gemm1 stage (A,Bg,Bu fp16) = 30720
#define ST2B    (ATILEB + BTILEB) // gemm2 stage (A fp16, B fp32) = 28672
#define SMEM1   (3*ST1B + 512)   // 92672 (3-stage)
#define SMEM2   (3*ST2B + 1024)  // 87040 (3-stage)

// ---------------- gemm1: h = silu(X Wg^T) * (X Wu^T), all fp16 ---------------
__global__ __launch_bounds__(256, 1) void gemm1_kernel() {
    int e = blockIdx.z;
    int cnt = g_counts[e];
    int mbase = blockIdx.y * 128;
    if (mbase >= cnt) return;
    int off = g_offsets[e];
    int nbase = blockIdx.x * 128;

    extern __shared__ char sm[];
    uint32_t sb = smem_u32(sm);
    int* stok = (int*)(sm + 3 * ST1B);
    int tid = threadIdx.x;

    if (tid < 128) {
        int m = mbase + tid;
        stok[tid] = g_sorted_tok[off + (m < cnt ? m : cnt - 1)];
    }
    __syncthreads();

    const __half* wgE = g_wgh + (size_t)e * FFN * DIM + (size_t)nbase * DIM;
    const __half* wuE = g_wuh + (size_t)e * FFN * DIM + (size_t)nbase * DIM;

    const __half *pa[4], *pg[4], *pu[4];
    uint32_t so[4];
#pragma unroll
    for (int j = 0; j < 4; j++) {
        int s = tid + j * 256;
        int r = s >> 3, sg = s & 7;
        pa[j] = g_xh + (size_t)stok[r] * DIM + sg * 4;
        pg[j] = wgE + (size_t)r * DIM + sg * 4;
        pu[j] = wuE + (size_t)r * DIM + sg * 4;
        so[j] = (uint32_t)(r * HROWB + sg * 8);
    }

#define ISSUE1(k0, s)                                                       \
    do {                                                                    \
        uint32_t base = sb + (s) * ST1B;                                    \
        _Pragma("unroll")                                                   \
        for (int j = 0; j < 4; j++) {                                       \
            cp8(base + so[j],              pa[j] + (k0));                   \
            cp8(base + ATILEB + so[j],     pg[j] + (k0));                   \
            cp8(base + 2*ATILEB + so[j],   pu[j] + (k0));                   \
        }                                                                   \
        cp_commit();                                                        \
    } while (0)

    int warp = tid >> 5, lane = tid & 31;
    int wm = warp >> 2, wn = warp & 3;        // 2 x 4
    int lr = lane >> 2, lc = lane & 3;

    float cg[4][4][4], cu[4][4][4];
#pragma unroll
    for (int a = 0; a < 4; a++)
#pragma unroll
        for (int b = 0; b < 4; b++)
#pragma unroll
            for (int r = 0; r < 4; r++) { cg[a][b][r] = 0.f; cu[a][b][r] = 0.f; }

    ISSUE1(0, 0);
    ISSUE1(KC, 1);

    const int NK = DIM / KC;   // 64
#pragma unroll 1
    for (int kt = 0; kt < NK; kt++) {
        cp_wait1();
        __syncthreads();
        if (kt + 2 < NK) {
            ISSUE1((kt + 2) * KC, (kt + 2) % 3);
        } else {
            cp_commit();
        }
        int s = kt % 3;
        const __half (*As)[HPITCH] = (const __half (*)[HPITCH])(sm + s * ST1B);
        const __half (*Bg)[HPITCH] = (const __half (*)[HPITCH])(sm + s * ST1B + ATILEB);
        const __half (*Bu)[HPITCH] = (const __half (*)[HPITCH])(sm + s * ST1B + 2 * ATILEB);
#pragma unroll
        for (int kk = 0; kk < 2; kk++) {
            int kb = kk * 16;
            int c  = kb + 2 * lc;
            uint32_t a[4][4];
#pragma unroll
            for (int mf = 0; mf < 4; mf++) {
                int r = wm * 64 + mf * 16 + lr;
                a[mf][0] = *(const uint32_t*)&As[r][c];
                a[mf][1] = *(const uint32_t*)&As[r + 8][c];
                a[mf][2] = *(const uint32_t*)&As[r][c + 8];
                a[mf][3] = *(const uint32_t*)&As[r + 8][c + 8];
            }
#pragma unroll
            for (int nf = 0; nf < 4; nf++) {
                int col = wn * 32 + nf * 8 + lr;
                uint32_t bg0 = *(const uint32_t*)&Bg[col][c];
                uint32_t bg1 = *(const uint32_t*)&Bg[col][c + 8];
                uint32_t bu0 = *(const uint32_t*)&Bu[col][c];
                uint32_t bu1 = *(const uint32_t*)&Bu[col][c + 8];
#pragma unroll
                for (int mf = 0; mf < 4; mf++) {
                    mma_f16(cg[mf][nf], a[mf][0], a[mf][1], a[mf][2], a[mf][3], bg0, bg1);
                    mma_f16(cu[mf][nf], a[mf][0], a[mf][1], a[mf][2], a[mf][3], bu0, bu1);
                }
            }
        }
    }

    // epilogue: h = silu(g) * u -> fp16
#pragma unroll
    for (int mf = 0; mf < 4; mf++) {
#pragma unroll
        for (int half = 0; half < 2; half++) {
            int mrow = wm * 64 + mf * 16 + lr + half * 8;
            int m = mbase + mrow;
            if (m < cnt) {
                __half* hp = g_hh + (size_t)(off + m) * FFN + nbase + wn * 32;
#pragma unroll
                for (int nf = 0; nf < 4; nf++) {
                    float g0 = cg[mf][nf][half * 2 + 0];
                    float g1 = cg[mf][nf][half * 2 + 1];
                    float u0 = cu[mf][nf][half * 2 + 0];
                    float u1 = cu[mf][nf][half * 2 + 1];
                    float h0 = u0 * g0 / (1.f + __expf(-g0));
                    float h1 = u1 * g1 / (1.f + __expf(-g1));
                    *(__half2*)(hp + nf * 8 + lc * 2) = __floats2half2_rn(h0, h1);
                }
            }
        }
    }
#undef ISSUE1
}

// ---------------- gemm2: out += w * (h Wo^T), Wo read as fp32 ----------------
__global__ __launch_bounds__(256, 1) void gemm2_kernel(
    const float* __restrict__ wout,
    float* __restrict__ out) {
    int e = blockIdx.z;
    int cnt = g_counts[e];
    int mbase = blockIdx.y * 128;
    if (mbase >= cnt) return;
    int off = g_offsets[e];
    int nbase = blockIdx.x * 128;

    extern __shared__ char sm[];
    uint32_t sb = smem_u32(sm);
    int*   stok = (int*)(sm + 3 * ST2B);
    float* swt  = (float*)(sm + 3 * ST2B + 512);
    int tid = threadIdx.x;

    if (tid < 128) {
        int m = mbase + tid;
        int mc = m < cnt ? m : cnt - 1;
        stok[tid] = g_sorted_tok[off + mc];
        swt[tid]  = (m < cnt) ? g_sorted_w[off + m] : 0.f;
    }
    __syncthreads();

    const float* woE = wout + (size_t)e * DIM * FFN + (size_t)nbase * FFN;

    const __half* paA[2];
    uint32_t soA[2];
#pragma unroll
    for (int j = 0; j < 2; j++) {
        int s = tid + j * 256;
        int r = s >> 2, sg = s & 3;
        int mc = mbase + r; if (mc > cnt - 1) mc = cnt - 1;
        paA[j] = g_hh + (size_t)(off + mc) * FFN + sg * 8;
        soA[j] = (uint32_t)(r * HROWB + sg * 16);
    }
    const float* pb[4];
    uint32_t soB[4];
#pragma unroll
    for (int j = 0; j < 4; j++) {
        int s = tid + j * 256;
        int r = s >> 3, sg = s & 7;
        pb[j] = woE + (size_t)r * FFN + sg * 4;
        soB[j] = (uint32_t)(r * FROWB + sg * 16);
    }

#define ISSUE2(k0, s)                                                       \
    do {                                                                    \
        uint32_t base = sb + (s) * ST2B;                                    \
        _Pragma("unroll")                                                   \
        for (int j = 0; j < 2; j++)                                         \
            cp16g(base + soA[j], paA[j] + (k0));                            \
        _Pragma("unroll")                                                   \
        for (int j = 0; j < 4; j++)                                         \
            cp16g(base + ATILEB + soB[j], pb[j] + (k0));                    \
        cp_commit();                                                        \
    } while (0)

    int warp = tid >> 5, lane = tid & 31;
    int wm = warp >> 2, wn = warp & 3;
    int lr = lane >> 2, lc = lane & 3;

    float cc[4][4][4];
#pragma unroll
    for (int a = 0; a < 4; a++)
#pragma unroll
        for (int b = 0; b < 4; b++)
#pragma unroll
            for (int r = 0; r < 4; r++) cc[a][b][r] = 0.f;

    ISSUE2(0, 0);
    ISSUE2(KC, 1);

    const int NK = FFN / KC;   // 176
#pragma unroll 1
    for (int kt = 0; kt < NK; kt++) {
        cp_wait1();
        __syncthreads();
        if (kt + 2 < NK) {
            ISSUE2((kt + 2) * KC, (kt + 2) % 3);
        } else {
            cp_commit();
        }
        int s = kt % 3;
        const __half (*As)[HPITCH] = (const __half (*)[HPITCH])(sm + s * ST2B);
        const float (*Bs)[FPITCH] = (const float (*)[FPITCH])(sm + s * ST2B + ATILEB);
#pragma unroll
        for (int kk = 0; kk < 2; kk++) {
            int kb = kk * 16;
            int ch = kb + 2 * lc;
            uint32_t a[4][4];
#pragma unroll
            for (int mf = 0; mf < 4; mf++) {
                int r = wm * 64 + mf * 16 + lr;
                a[mf][0] = *(const uint32_t*)&As[r][ch];
                a[mf][1] = *(const uint32_t*)&As[r + 8][ch];
                a[mf][2] = *(const uint32_t*)&As[r][ch + 8];
                a[mf][3] = *(const uint32_t*)&As[r + 8][ch + 8];
            }
#pragma unroll
            for (int nf = 0; nf < 4; nf++) {
                int col = wn * 32 + nf * 8 + lr;
                float2 w0 = *(const float2*)&Bs[col][ch];
                float2 w1 = *(const float2*)&Bs[col][ch + 8];
                uint32_t b0 = packh2(w0.x, w0.y), b1 = packh2(w1.x, w1.y);
#pragma unroll
                for (int mf = 0; mf < 4; mf++)
                    mma_f16(cc[mf][nf], a[mf][0], a[mf][1], a[mf][2], a[mf][3], b0, b1);
            }
        }
    }

    // epilogue: out += w * y
#pragma unroll
    for (int mf = 0; mf < 4; mf++) {
#pragma unroll
        for (int half = 0; half < 2; half++) {
            int mrow = wm * 64 + mf * 16 + lr + half * 8;
            int m = mbase + mrow;
            if (m < cnt) {
                float wgt = swt[mrow];
                float* op = out + (size_t)stok[mrow] * DIM + nbase + wn * 32;
#pragma unroll
                for (int nf = 0; nf < 4; nf++) {
                    atomicAdd(op + nf * 8 + lc * 2,     cc[mf][nf][half * 2 + 0] * wgt);
                    atomicAdd(op + nf * 8 + lc * 2 + 1, cc[mf][nf][half * 2 + 1] * wgt);
                }
            }
        }
    }
#undef ISSUE2
}

// ---------------- launch -----------------------------------------------------
extern "C" void kernel_launch(void* const* d_in, const int* in_sizes, int n_in,
                              void* d_out, int out_size) {
    const float* x    = (const float*)d_in[0];
    const float* gw   = (const float*)d_in[1];
    const float* wg   = (const float*)d_in[2];
    const float* wu   = (const float*)d_in[3];
    const float* wo   = (const float*)d_in[4];
    const float* bias = (const float*)d_in[5];
    float* out = (float*)d_out;

    cudaFuncSetAttribute(gemm1_kernel, cudaFuncAttributeMaxDynamicSharedMemorySize, SMEM1);
    cudaFuncSetAttribute(gemm2_kernel, cudaFuncAttributeMaxDynamicSharedMemorySize, SMEM2);

    __half *xh, *wgh, *wuh;
    cudaGetSymbolAddress((void**)&xh,  g_xh);
    cudaGetSymbolAddress((void**)&wgh, g_wgh);
    cudaGetSymbolAddress((void**)&wuh, g_wuh);

    const int nW4 = NE * FFN * DIM / 4;   // 23068672
    const int nX4 = T_TOK * DIM / 4;      // 2097152

    zero_kernel<<<1, 32>>>();
    router_kernel<<<T_TOK, 256>>>(x, gw);
    scan_kernel<<<1, 32>>>();
    scatter_kernel<<<(T_TOK + 255) / 256, 256>>>();
    init_out_kernel<<<(T_TOK * DIM) / 256, 256>>>(out, bias);
    cvt_kernel<<<nX4 / 256, 256>>>(x, xh, nX4);
    cvt2_kernel<<<2 * nW4 / 256, 256>>>(wg, wgh, wu, wuh, nW4);
    gemm1_kernel<<<dim3(FFN / 128, T_TOK / 128, NE), 256, SMEM1>>>();
    gemm2_kernel<<<dim3(DIM / 128, T_TOK / 128, NE), 256, SMEM2>>>(wo, out);
}